// round 5
// baseline (speedup 1.0000x reference)
#include <cuda_runtime.h>
#include <cuda_bf16.h>

// PyramidROIAlign R5: TWO boxes per block (grid=1000 -> single resident wave,
// no tail). 4 groups of 64 float4-lanes stream 98 cells. Cell params fetched
// as 2x LDS.128.

#define POOL_W 7
#define NCELLS 49
#define NCH    256
#define NBOXES 1000
#define NBATCH 2

struct __align__(16) CellParam {
    int   o00, o01, o10, o11;   // corner byte offsets (channel 0) rel. to feat base
    float wx, wy, vm, pad;
};

__global__ __launch_bounds__(256, 8) void pyramid_roi_align_kernel(
    const float* __restrict__ boxes,
    const float* __restrict__ p3,      // [B,128,128,C]
    const float* __restrict__ p4,      // [B,64,64,C]
    const float* __restrict__ p5,      // [B,32,32,C]
    float* __restrict__ out)           // [B*N, 7, 7, C]
{
    __shared__ CellParam cp[2 * NCELLS];
    __shared__ const char* featb[2];

    const int tid   = threadIdx.x;
    const int local = tid >> 6;        // group 0..3
    const int lane  = tid & 63;        // float4 channel group
    const int box0  = blockIdx.x * 2;  // first of the 2 boxes

    // ---- phase 1: per-cell params for both boxes (threads 0..97) ----
    if (tid < 2 * NCELLS) {
        const int sel  = (tid >= NCELLS) ? 1 : 0;
        const int cell = tid - sel * NCELLS;
        const int gbox = box0 + sel;
        const int b    = (gbox >= NBOXES) ? 1 : 0;

        const float y1 = __ldg(boxes + gbox * 4 + 0);
        const float x1 = __ldg(boxes + gbox * 4 + 1);
        const float y2 = __ldg(boxes + gbox * 4 + 2);
        const float x2 = __ldg(boxes + gbox * 4 + 3);
        const float h  = y2 - y1;
        const float w  = x2 - x1;

        float lvlf = ceilf(5.0f + logf(h * w) / 0.6931471805599453f);
        lvlf = fminf(fmaxf(lvlf, 3.0f), 5.0f);
        const int level = (int)lvlf;

        const float* feat;
        int HW;
        if (level == 3)      { feat = p3; HW = 128; }
        else if (level == 4) { feat = p4; HW = 64;  }
        else                 { feat = p5; HW = 32;  }

        const float Hm1 = (float)(HW - 1);
        const int   iy  = cell / POOL_W;
        const int   ix  = cell - iy * POOL_W;
        // exact reference rounding order
        const float stepy = __fdiv_rn(__fmul_rn(h, Hm1), 6.0f);
        const float stepx = __fdiv_rn(__fmul_rn(w, Hm1), 6.0f);
        const float ys = __fadd_rn(__fmul_rn(y1, Hm1), __fmul_rn((float)iy, stepy));
        const float xs = __fadd_rn(__fmul_rn(x1, Hm1), __fmul_rn((float)ix, stepx));

        const bool valid = (ys >= 0.0f) & (ys <= Hm1) & (xs >= 0.0f) & (xs <= Hm1);

        const float y0f = floorf(ys);
        const float x0f = floorf(xs);

        const int y0i = (int)fminf(fmaxf(y0f, 0.0f), Hm1);
        const int y1i = (int)fminf(fmaxf(y0f + 1.0f, 0.0f), Hm1);
        const int x0i = (int)fminf(fmaxf(x0f, 0.0f), Hm1);
        const int x1i = (int)fminf(fmaxf(x0f + 1.0f, 0.0f), Hm1);

        const int rowbytes = HW * NCH * 4;
        CellParam p;
        p.o00 = y0i * rowbytes + x0i * (NCH * 4);
        p.o01 = y0i * rowbytes + x1i * (NCH * 4);
        p.o10 = y1i * rowbytes + x0i * (NCH * 4);
        p.o11 = y1i * rowbytes + x1i * (NCH * 4);
        p.wx  = xs - x0f;
        p.wy  = ys - y0f;
        p.vm  = valid ? 1.0f : 0.0f;
        p.pad = 0.0f;
        cp[tid] = p;

        if (cell == 0)
            featb[sel] = (const char*)(feat + (size_t)b * HW * HW * NCH);
    }
    __syncthreads();

    // ---- phase 2: stream channels for both boxes' 98 cells ----
    const char* fb0 = featb[0] + lane * 16;
    const char* fb1 = featb[1] + lane * 16;
    float4* outp = (float4*)out + (size_t)box0 * NCELLS * (NCH / 4) + lane;

    #pragma unroll 2
    for (int c = local; c < 2 * NCELLS; c += 4) {
        const int4   oo = ((const int4*)&cp[c])[0];
        const float4 ww = ((const float4*)&cp[c])[1];
        const float  wx = ww.x;
        const float  wy = ww.y;
        const float  vm = ww.z;

        const char* bp = (c < NCELLS) ? fb0 : fb1;

        const float4 v00 = __ldg((const float4*)(bp + oo.x));
        const float4 v01 = __ldg((const float4*)(bp + oo.y));
        const float4 v10 = __ldg((const float4*)(bp + oo.z));
        const float4 v11 = __ldg((const float4*)(bp + oo.w));

        const float owx = 1.0f - wx;
        const float owy = 1.0f - wy;

        float4 o;
        o.x = ((v00.x * owx + v01.x * wx) * owy + (v10.x * owx + v11.x * wx) * wy) * vm;
        o.y = ((v00.y * owx + v01.y * wx) * owy + (v10.y * owx + v11.y * wx) * wy) * vm;
        o.z = ((v00.z * owx + v01.z * wx) * owy + (v10.z * owx + v11.z * wx) * wy) * vm;
        o.w = ((v00.w * owx + v01.w * wx) * owy + (v10.w * owx + v11.w * wx) * wy) * vm;

        __stcs(outp + (size_t)c * (NCH / 4), o);
    }
}

extern "C" void kernel_launch(void* const* d_in, const int* in_sizes, int n_in,
                              void* d_out, int out_size) {
    const float* boxes = (const float*)d_in[0];
    const float* p3    = (const float*)d_in[2];
    const float* p4    = (const float*)d_in[3];
    const float* p5    = (const float*)d_in[4];
    float* out = (float*)d_out;

    pyramid_roi_align_kernel<<<NBATCH * NBOXES / 2, 256>>>(boxes, p3, p4, p5, out);
}

// round 6
// speedup vs baseline: 1.0946x; 1.0946x over previous
#include <cuda_runtime.h>
#include <cuda_bf16.h>

// PyramidROIAlign R6: R3 structure (one block/box, 4 groups x 64 float4-lanes),
// but bilinear computed as a precomputed 4-weight dot product (16 FFMA / float4).
// Phase 1 keeps the reference's exact rounding for floor/validity decisions.

#define POOL_W 7
#define NCELLS 49
#define NCH    256
#define NBOXES 1000
#define NBATCH 2

struct __align__(16) CellParam {
    int   o00, o01, o10, o11;   // corner byte offsets (channel 0)
    float a00, a01, a10, a11;   // bilinear weights * validity
};

__global__ __launch_bounds__(256, 8) void pyramid_roi_align_kernel(
    const float* __restrict__ boxes,
    const float* __restrict__ p3,      // [B,128,128,C]
    const float* __restrict__ p4,      // [B,64,64,C]
    const float* __restrict__ p5,      // [B,32,32,C]
    float* __restrict__ out)           // [B*N, 7, 7, C]
{
    __shared__ CellParam cp[NCELLS];

    const int box   = blockIdx.x;
    const int tid   = threadIdx.x;
    const int local = tid >> 6;        // cell group 0..3
    const int lane  = tid & 63;        // float4 channel group
    const int b     = (box >= NBOXES) ? 1 : 0;

    // ---- box scalars (broadcast loads; all threads) ----
    const float y1 = __ldg(boxes + box * 4 + 0);
    const float x1 = __ldg(boxes + box * 4 + 1);
    const float y2 = __ldg(boxes + box * 4 + 2);
    const float x2 = __ldg(boxes + box * 4 + 3);
    const float h  = y2 - y1;
    const float w  = x2 - x1;

    float lvlf = ceilf(5.0f + logf(h * w) / 0.6931471805599453f);
    lvlf = fminf(fmaxf(lvlf, 3.0f), 5.0f);
    const int level = (int)lvlf;

    const float* feat;
    int HW;
    if (level == 3)      { feat = p3; HW = 128; }
    else if (level == 4) { feat = p4; HW = 64;  }
    else                 { feat = p5; HW = 32;  }

    // ---- phase 1: per-cell params (threads 0..48); exact reference rounding
    //      for the discrete decisions (floor, clamp, validity) ----
    if (tid < NCELLS) {
        const float Hm1 = (float)(HW - 1);
        const int   iy  = tid / POOL_W;
        const int   ix  = tid - iy * POOL_W;
        const float stepy = __fdiv_rn(__fmul_rn(h, Hm1), 6.0f);
        const float stepx = __fdiv_rn(__fmul_rn(w, Hm1), 6.0f);
        const float ys = __fadd_rn(__fmul_rn(y1, Hm1), __fmul_rn((float)iy, stepy));
        const float xs = __fadd_rn(__fmul_rn(x1, Hm1), __fmul_rn((float)ix, stepx));

        const bool valid = (ys >= 0.0f) & (ys <= Hm1) & (xs >= 0.0f) & (xs <= Hm1);
        const float vm = valid ? 1.0f : 0.0f;

        const float y0f = floorf(ys);
        const float x0f = floorf(xs);
        const float wy  = ys - y0f;
        const float wx  = xs - x0f;
        const float owy = 1.0f - wy;
        const float owx = 1.0f - wx;

        const int y0i = (int)fminf(fmaxf(y0f, 0.0f), Hm1);
        const int y1i = (int)fminf(fmaxf(y0f + 1.0f, 0.0f), Hm1);
        const int x0i = (int)fminf(fmaxf(x0f, 0.0f), Hm1);
        const int x1i = (int)fminf(fmaxf(x0f + 1.0f, 0.0f), Hm1);

        const int rowbytes = HW * NCH * 4;
        CellParam p;
        p.o00 = y0i * rowbytes + x0i * (NCH * 4);
        p.o01 = y0i * rowbytes + x1i * (NCH * 4);
        p.o10 = y1i * rowbytes + x0i * (NCH * 4);
        p.o11 = y1i * rowbytes + x1i * (NCH * 4);
        p.a00 = owx * owy * vm;
        p.a01 = wx  * owy * vm;
        p.a10 = owx * wy  * vm;
        p.a11 = wx  * wy  * vm;
        cp[tid] = p;
    }
    __syncthreads();

    // ---- phase 2: stream channels ----
    const char* basep = (const char*)(feat + (size_t)b * HW * HW * NCH) + lane * 16;
    float4* outp = (float4*)out + (size_t)box * NCELLS * (NCH / 4) + lane;

    #pragma unroll 2
    for (int c = local; c < NCELLS; c += 4) {
        const int4   oo = ((const int4*)&cp[c])[0];
        const float4 aa = ((const float4*)&cp[c])[1];

        const float4 v00 = __ldg((const float4*)(basep + oo.x));
        const float4 v01 = __ldg((const float4*)(basep + oo.y));
        const float4 v10 = __ldg((const float4*)(basep + oo.z));
        const float4 v11 = __ldg((const float4*)(basep + oo.w));

        float4 o;
        o.x = v00.x * aa.x + v01.x * aa.y + v10.x * aa.z + v11.x * aa.w;
        o.y = v00.y * aa.x + v01.y * aa.y + v10.y * aa.z + v11.y * aa.w;
        o.z = v00.z * aa.x + v01.z * aa.y + v10.z * aa.z + v11.z * aa.w;
        o.w = v00.w * aa.x + v01.w * aa.y + v10.w * aa.z + v11.w * aa.w;

        __stcs(outp + (size_t)c * (NCH / 4), o);
    }
}

extern "C" void kernel_launch(void* const* d_in, const int* in_sizes, int n_in,
                              void* d_out, int out_size) {
    const float* boxes = (const float*)d_in[0];
    const float* p3    = (const float*)d_in[2];
    const float* p4    = (const float*)d_in[3];
    const float* p5    = (const float*)d_in[4];
    float* out = (float*)d_out;

    pyramid_roi_align_kernel<<<NBATCH * NBOXES, 256>>>(boxes, p3, p4, p5, out);
}